// round 3
// baseline (speedup 1.0000x reference)
#include <cuda_runtime.h>
#include <math.h>
#include <stdint.h>

#define N_NODES 40000
#define E_EDGES 640000
#define D_IN    32
#define D_G     64
#define D_F     128

#define TILE_E  128
// smem floats: ean 128*68, wf1 64*136, wf2 128*136, t 128*136
#define EAN_STR 68
#define W_STR   136
#define SMEM_FLOATS (128*EAN_STR + 64*W_STR + 128*W_STR + 128*W_STR)
#define SMEM_BYTES  (SMEM_FLOATS * 4)    // 208896

// ---------------- scratch ----------------
__device__ float g_h[N_NODES * D_F];
__device__ float g_agg[N_NODES * D_F];
__device__ float g_messages[(size_t)E_EDGES * D_F];
__device__ int   g_rowptr[N_NODES + 1];

// ---------------- tf32 helpers ----------------
__device__ __forceinline__ void split_tf32(float x, uint32_t& hi, uint32_t& lo) {
    asm("cvt.rna.tf32.f32 %0, %1;" : "=r"(hi) : "f"(x));
    float r = x - __uint_as_float(hi);
    asm("cvt.rna.tf32.f32 %0, %1;" : "=r"(lo) : "f"(r));
}
__device__ __forceinline__ void mma8(float4& d, uint32_t a0, uint32_t a1, uint32_t a2,
                                     uint32_t a3, uint32_t b0, uint32_t b1) {
    asm volatile(
        "mma.sync.aligned.m16n8k8.row.col.f32.tf32.tf32.f32 "
        "{%0,%1,%2,%3},{%4,%5,%6,%7},{%8,%9},{%0,%1,%2,%3};\n"
        : "+f"(d.x), "+f"(d.y), "+f"(d.z), "+f"(d.w)
        : "r"(a0), "r"(a1), "r"(a2), "r"(a3), "r"(b0), "r"(b1));
}

// ---------------- K1: h = x @ W_proj + b_proj ----------------
__global__ __launch_bounds__(128) void proj_kernel(const float* __restrict__ x,
                                                   const float* __restrict__ W,
                                                   const float* __restrict__ b) {
    const int f  = threadIdx.x;
    const int nb = blockIdx.x * 8;
    __shared__ float xs[8 * D_IN];
    xs[f]       = x[nb * D_IN + f];
    xs[f + 128] = x[nb * D_IN + f + 128];
    float w[D_IN];
#pragma unroll
    for (int k = 0; k < D_IN; k++) w[k] = W[k * D_F + f];
    const float bias = b[f];
    __syncthreads();
#pragma unroll
    for (int n = 0; n < 8; n++) {
        float acc = bias;
#pragma unroll
        for (int k = 0; k < D_IN; k++) acc = fmaf(xs[n * D_IN + k], w[k], acc);
        g_h[(nb + n) * D_F + f] = acc;
    }
}

// ---------------- K2: row_ptr ----------------
__global__ void rowptr_kernel(const int* __restrict__ tgt) {
    int n = blockIdx.x * blockDim.x + threadIdx.x;
    if (n > N_NODES) return;
    if (n == N_NODES) { g_rowptr[n] = E_EDGES; return; }
    int lo = 0, hi = E_EDGES;
    while (lo < hi) {
        int mid = (lo + hi) >> 1;
        if (tgt[mid] < n) lo = mid + 1; else hi = mid;
    }
    g_rowptr[n] = lo;
}

// ---------------- K3: edge filter MLP (3xTF32 tensor cores) ----------------
// Block: 256 threads (8 warps), 128 edges/block, 5000 blocks.
// Warp w: m-tiles (w&1)*4+mi (mi<4, 16 rows each), n-tiles (w>>1)*4+nj (nj<4, 8 cols).
__global__ __launch_bounds__(256) void edge_kernel(
    const int* __restrict__ src,
    const float* __restrict__ edge_attr,
    const float* __restrict__ Wf1, const float* __restrict__ bf1,
    const float* __restrict__ Wf2, const float* __restrict__ bf2,
    const float* __restrict__ nbr,
    float* __restrict__ attn_out)
{
    extern __shared__ float dsm[];
    float* ean_s = dsm;                          // [128][68]
    float* wf1_s = ean_s + 128 * EAN_STR;        // [64][136]
    float* wf2_s = wf1_s + 64 * W_STR;           // [128][136]
    float* t_s   = wf2_s + 128 * W_STR;          // [128][136]  (later reused for filters)

    const int tid  = threadIdx.x;
    const int lane = tid & 31;
    const int w    = tid >> 5;
    const int grp  = lane >> 2;   // 0..7
    const int tg   = lane & 3;    // 0..3
    const int ebase = blockIdx.x * TILE_E;

    // ---- stage Wf1, Wf2 (strided, conflict-free layout) ----
#pragma unroll
    for (int p = tid; p < 64 * 32; p += 256) {
        int r = p >> 5, c = p & 31;
        ((float4*)(wf1_s + r * W_STR))[c] = ((const float4*)(Wf1 + r * D_F))[c];
    }
#pragma unroll
    for (int p = tid; p < 128 * 32; p += 256) {
        int r = p >> 5, c = p & 31;
        ((float4*)(wf2_s + r * W_STR))[c] = ((const float4*)(Wf2 + r * D_F))[c];
    }

    // ---- load + normalize edge_attr: 2 threads per row, 32 floats each ----
    {
        const int erow = tid >> 1;
        const int half = tid & 1;
        float4 va[8];
        const float4* ea4 = (const float4*)(edge_attr + (size_t)(ebase + erow) * D_G) + half * 8;
        float ss = 0.f;
#pragma unroll
        for (int j = 0; j < 8; j++) {
            va[j] = ea4[j];
            ss += va[j].x * va[j].x + va[j].y * va[j].y + va[j].z * va[j].z + va[j].w * va[j].w;
        }
        ss += __shfl_xor_sync(0xffffffffu, ss, 1);
        const float inv = 1.0f / (sqrtf(ss) + 1e-8f);
        float4* dst = (float4*)(ean_s + erow * EAN_STR) + half * 8;
#pragma unroll
        for (int j = 0; j < 8; j++) {
            va[j].x *= inv; va[j].y *= inv; va[j].z *= inv; va[j].w *= inv;
            dst[j] = va[j];
        }
    }
    __syncthreads();

    const int mrow0 = (w & 1) * 64;
    const int nb0   = (w >> 1) * 32;

    float4 C[4][4];
#pragma unroll
    for (int mi = 0; mi < 4; mi++)
#pragma unroll
        for (int nj = 0; nj < 4; nj++) C[mi][nj] = make_float4(0.f, 0.f, 0.f, 0.f);

    // ---- GEMM1: t = tanh(ean @ Wf1 + bf1), K = 64 ----
#pragma unroll
    for (int kk = 0; kk < 8; kk++) {
        const int k0 = kk * 8;
        uint32_t Ahi[4][4], Alo[4][4];
#pragma unroll
        for (int mi = 0; mi < 4; mi++) {
            const int r = mrow0 + mi * 16;
            split_tf32(ean_s[(r + grp)     * EAN_STR + k0 + tg],     Ahi[mi][0], Alo[mi][0]);
            split_tf32(ean_s[(r + grp + 8) * EAN_STR + k0 + tg],     Ahi[mi][1], Alo[mi][1]);
            split_tf32(ean_s[(r + grp)     * EAN_STR + k0 + tg + 4], Ahi[mi][2], Alo[mi][2]);
            split_tf32(ean_s[(r + grp + 8) * EAN_STR + k0 + tg + 4], Ahi[mi][3], Alo[mi][3]);
        }
        uint32_t Bhi[4][2], Blo[4][2];
#pragma unroll
        for (int nj = 0; nj < 4; nj++) {
            const int n = nb0 + nj * 8 + grp;
            split_tf32(wf1_s[(k0 + tg)     * W_STR + n], Bhi[nj][0], Blo[nj][0]);
            split_tf32(wf1_s[(k0 + tg + 4) * W_STR + n], Bhi[nj][1], Blo[nj][1]);
        }
#pragma unroll
        for (int mi = 0; mi < 4; mi++)
#pragma unroll
            for (int nj = 0; nj < 4; nj++) {
                mma8(C[mi][nj], Ahi[mi][0], Ahi[mi][1], Ahi[mi][2], Ahi[mi][3], Bhi[nj][0], Bhi[nj][1]);
                mma8(C[mi][nj], Ahi[mi][0], Ahi[mi][1], Ahi[mi][2], Ahi[mi][3], Blo[nj][0], Blo[nj][1]);
                mma8(C[mi][nj], Alo[mi][0], Alo[mi][1], Alo[mi][2], Alo[mi][3], Bhi[nj][0], Bhi[nj][1]);
            }
    }

    // bias + tanh -> t_s
#pragma unroll
    for (int nj = 0; nj < 4; nj++) {
        const int n = nb0 + nj * 8 + 2 * tg;
        const float b0 = __ldg(bf1 + n), b1 = __ldg(bf1 + n + 1);
#pragma unroll
        for (int mi = 0; mi < 4; mi++) {
            const int r = mrow0 + mi * 16;
            float4 c = C[mi][nj];
            float2 lo2 = make_float2(tanhf(c.x + b0), tanhf(c.y + b1));
            float2 hi2 = make_float2(tanhf(c.z + b0), tanhf(c.w + b1));
            *(float2*)(t_s + (r + grp)     * W_STR + n) = lo2;
            *(float2*)(t_s + (r + grp + 8) * W_STR + n) = hi2;
        }
    }
    __syncthreads();

    // ---- GEMM2: filters = t @ Wf2 + bf2, K = 128 ----
#pragma unroll
    for (int mi = 0; mi < 4; mi++)
#pragma unroll
        for (int nj = 0; nj < 4; nj++) C[mi][nj] = make_float4(0.f, 0.f, 0.f, 0.f);

#pragma unroll
    for (int kk = 0; kk < 16; kk++) {
        const int k0 = kk * 8;
        uint32_t Ahi[4][4], Alo[4][4];
#pragma unroll
        for (int mi = 0; mi < 4; mi++) {
            const int r = mrow0 + mi * 16;
            split_tf32(t_s[(r + grp)     * W_STR + k0 + tg],     Ahi[mi][0], Alo[mi][0]);
            split_tf32(t_s[(r + grp + 8) * W_STR + k0 + tg],     Ahi[mi][1], Alo[mi][1]);
            split_tf32(t_s[(r + grp)     * W_STR + k0 + tg + 4], Ahi[mi][2], Alo[mi][2]);
            split_tf32(t_s[(r + grp + 8) * W_STR + k0 + tg + 4], Ahi[mi][3], Alo[mi][3]);
        }
        uint32_t Bhi[4][2], Blo[4][2];
#pragma unroll
        for (int nj = 0; nj < 4; nj++) {
            const int n = nb0 + nj * 8 + grp;
            split_tf32(wf2_s[(k0 + tg)     * W_STR + n], Bhi[nj][0], Blo[nj][0]);
            split_tf32(wf2_s[(k0 + tg + 4) * W_STR + n], Bhi[nj][1], Blo[nj][1]);
        }
#pragma unroll
        for (int mi = 0; mi < 4; mi++)
#pragma unroll
            for (int nj = 0; nj < 4; nj++) {
                mma8(C[mi][nj], Ahi[mi][0], Ahi[mi][1], Ahi[mi][2], Ahi[mi][3], Bhi[nj][0], Bhi[nj][1]);
                mma8(C[mi][nj], Ahi[mi][0], Ahi[mi][1], Ahi[mi][2], Ahi[mi][3], Blo[nj][0], Blo[nj][1]);
                mma8(C[mi][nj], Alo[mi][0], Alo[mi][1], Alo[mi][2], Alo[mi][3], Bhi[nj][0], Bhi[nj][1]);
            }
    }
    __syncthreads();   // all t_s reads done before overwrite with filters

    // bias -> filters into t_s (reuse)
#pragma unroll
    for (int nj = 0; nj < 4; nj++) {
        const int n = nb0 + nj * 8 + 2 * tg;
        const float b0 = __ldg(bf2 + n), b1 = __ldg(bf2 + n + 1);
#pragma unroll
        for (int mi = 0; mi < 4; mi++) {
            const int r = mrow0 + mi * 16;
            float4 c = C[mi][nj];
            *(float2*)(t_s + (r + grp)     * W_STR + n) = make_float2(c.x + b0, c.y + b1);
            *(float2*)(t_s + (r + grp + 8) * W_STR + n) = make_float2(c.z + b0, c.w + b1);
        }
    }
    __syncthreads();

    // ---- epilogue: messages = h[src] * filters; attn = messages . nbr ----
    {
        const int row = tid >> 1;            // 0..127
        const int cb  = (tid & 1) * 64;      // col half
        const int e   = ebase + row;
        const int sn  = src[e];
        const float4* hrow = (const float4*)(g_h + (size_t)sn * D_F + cb);
        const float4* frow = (const float4*)(t_s + row * W_STR + cb);
        const float4* nb4  = (const float4*)(nbr + cb);
        float4* mrow = (float4*)(g_messages + (size_t)e * D_F + cb);
        float p = 0.f;
#pragma unroll
        for (int j = 0; j < 16; j++) {
            float4 f = frow[j];
            float4 h = hrow[j];
            float4 n4 = nb4[j];
            float4 m;
            m.x = f.x * h.x; m.y = f.y * h.y; m.z = f.z * h.z; m.w = f.w * h.w;
            mrow[j] = m;
            p += m.x * n4.x + m.y * n4.y + m.z * n4.z + m.w * n4.w;
        }
        p += __shfl_xor_sync(0xffffffffu, p, 1);
        if ((tid & 1) == 0) attn_out[e] = p;
    }
}

// ---------------- K4: segment softmax + aggregate ----------------
__global__ __launch_bounds__(256) void agg_kernel(const float* __restrict__ attn) {
    const int node = (blockIdx.x * blockDim.x + threadIdx.x) >> 5;
    const int lane = threadIdx.x & 31;
    if (node >= N_NODES) return;
    const int s = g_rowptr[node];
    const int e = g_rowptr[node + 1];

    float m = -INFINITY;
    for (int j = s + lane; j < e; j += 32) m = fmaxf(m, attn[j]);
#pragma unroll
    for (int off = 16; off; off >>= 1) m = fmaxf(m, __shfl_xor_sync(0xffffffffu, m, off));

    float ssum = 0.f;
    for (int j = s + lane; j < e; j += 32) ssum += expf(attn[j] - m);
#pragma unroll
    for (int off = 16; off; off >>= 1) ssum += __shfl_xor_sync(0xffffffffu, ssum, off);
    const float inv = (e > s) ? 1.0f / ssum : 0.0f;

    float4 acc = make_float4(0.f, 0.f, 0.f, 0.f);
    for (int j = s; j < e; j++) {
        float wgt = expf(attn[j] - m) * inv;
        float4 mm = ((const float4*)(g_messages + (size_t)j * D_F))[lane];
        acc.x = fmaf(wgt, mm.x, acc.x);
        acc.y = fmaf(wgt, mm.y, acc.y);
        acc.z = fmaf(wgt, mm.z, acc.z);
        acc.w = fmaf(wgt, mm.w, acc.w);
    }
    ((float4*)(g_agg + (size_t)node * D_F))[lane] = acc;
}

// ---------------- K5: out = tanh(agg @ Wo1 + bo1) @ Wo2 + bo2 ----------------
__global__ __launch_bounds__(256) void out_kernel(
    const float* __restrict__ Wo1, const float* __restrict__ bo1,
    const float* __restrict__ Wo2, const float* __restrict__ bo2,
    float* __restrict__ out)
{
    __shared__ float sm[64 * D_F];
    const int tid  = threadIdx.x;
    const int lane = tid & 31;
    const int w    = tid >> 5;
    const int nb   = blockIdx.x * 64;

    const float4* src4 = (const float4*)(g_agg + (size_t)nb * D_F);
#pragma unroll
    for (int j = 0; j < 8; j++)
        ((float4*)sm)[tid + 256 * j] = src4[tid + 256 * j];
    __syncthreads();

    float4 acc[8];
    {
        float4 b1 = *(const float4*)(bo1 + lane * 4);
#pragma unroll
        for (int i = 0; i < 8; i++) acc[i] = b1;
    }
    for (int k = 0; k < D_F; k++) {
        float4 wk = *(const float4*)(Wo1 + k * D_F + lane * 4);
#pragma unroll
        for (int i = 0; i < 8; i++) {
            float a = sm[(w * 8 + i) * D_F + k];
            acc[i].x = fmaf(a, wk.x, acc[i].x);
            acc[i].y = fmaf(a, wk.y, acc[i].y);
            acc[i].z = fmaf(a, wk.z, acc[i].z);
            acc[i].w = fmaf(a, wk.w, acc[i].w);
        }
    }
#pragma unroll
    for (int i = 0; i < 8; i++) {
        acc[i].x = tanhf(acc[i].x); acc[i].y = tanhf(acc[i].y);
        acc[i].z = tanhf(acc[i].z); acc[i].w = tanhf(acc[i].w);
    }
    __syncthreads();
#pragma unroll
    for (int i = 0; i < 8; i++)
        ((float4*)(sm + (w * 8 + i) * D_F))[lane] = acc[i];
    __syncthreads();

    float o[8];
    {
        float b2 = bo2[lane];
#pragma unroll
        for (int i = 0; i < 8; i++) o[i] = b2;
    }
    for (int k = 0; k < D_F; k++) {
        float wo = Wo2[k * D_IN + lane];
#pragma unroll
        for (int i = 0; i < 8; i++)
            o[i] = fmaf(sm[(w * 8 + i) * D_F + k], wo, o[i]);
    }
#pragma unroll
    for (int i = 0; i < 8; i++)
        out[(size_t)(nb + w * 8 + i) * D_IN + lane] = o[i];
}

// ---------------- launch ----------------
extern "C" void kernel_launch(void* const* d_in, const int* in_sizes, int n_in,
                              void* d_out, int out_size) {
    const float* x         = (const float*)d_in[0];
    const int*   edge_index= (const int*)d_in[1];
    const float* edge_attr = (const float*)d_in[2];
    const float* W_proj    = (const float*)d_in[3];
    const float* b_proj    = (const float*)d_in[4];
    const float* Wf1       = (const float*)d_in[5];
    const float* bf1       = (const float*)d_in[6];
    const float* Wf2       = (const float*)d_in[7];
    const float* bf2       = (const float*)d_in[8];
    const float* nbr       = (const float*)d_in[9];
    const float* Wo1       = (const float*)d_in[10];
    const float* bo1       = (const float*)d_in[11];
    const float* Wo2       = (const float*)d_in[12];
    const float* bo2       = (const float*)d_in[13];

    float* out      = (float*)d_out;
    float* attn_out = out + (size_t)N_NODES * D_IN;

    const int* src = edge_index;
    const int* tgt = edge_index + E_EDGES;

    cudaFuncSetAttribute(edge_kernel, cudaFuncAttributeMaxDynamicSharedMemorySize, SMEM_BYTES);

    proj_kernel<<<N_NODES / 8, 128>>>(x, W_proj, b_proj);
    rowptr_kernel<<<(N_NODES + 1 + 255) / 256, 256>>>(tgt);
    edge_kernel<<<E_EDGES / TILE_E, 256, SMEM_BYTES>>>(src, edge_attr, Wf1, bf1, Wf2, bf2,
                                                       nbr, attn_out);
    agg_kernel<<<(N_NODES * 32) / 256, 256>>>(attn_out);
    out_kernel<<<N_NODES / 64, 256>>>(Wo1, bo1, Wo2, bo2, out);
}

// round 6
// speedup vs baseline: 1.0743x; 1.0743x over previous
#include <cuda_runtime.h>
#include <math.h>
#include <stdint.h>

#define N_NODES 40000
#define E_EDGES 640000
#define D_IN    32
#define D_G     64
#define D_F     128

// ---------------- scratch (static device globals; no allocation) ----------------
__device__ float g_h[N_NODES * D_F];
__device__ float g_agg[N_NODES * D_F];
__device__ float g_messages[(size_t)E_EDGES * D_F];
__device__ int   g_rowptr[N_NODES + 1];

// ---------------- packed f32x2 helpers (Blackwell FFMA2 path) ----------------
__device__ __forceinline__ uint64_t pack2(float x, float y) {
    uint64_t r;
    asm("mov.b64 %0, {%1, %2};" : "=l"(r) : "f"(x), "f"(y));
    return r;
}
__device__ __forceinline__ void unpack2(uint64_t v, float& x, float& y) {
    asm("mov.b64 {%0, %1}, %2;" : "=f"(x), "=f"(y) : "l"(v));
}
__device__ __forceinline__ void ffma2(uint64_t& d, uint64_t a, uint64_t b) {
    asm("fma.rn.f32x2 %0, %1, %2, %0;" : "+l"(d) : "l"(a), "l"(b));
}

// ---------------- K1: h = x @ W_proj + b_proj ----------------
__global__ __launch_bounds__(128) void proj_kernel(const float* __restrict__ x,
                                                   const float* __restrict__ W,
                                                   const float* __restrict__ b) {
    const int f  = threadIdx.x;
    const int nb = blockIdx.x * 8;
    __shared__ float xs[8 * D_IN];
    xs[f]       = x[nb * D_IN + f];
    xs[f + 128] = x[nb * D_IN + f + 128];
    float w[D_IN];
#pragma unroll
    for (int k = 0; k < D_IN; k++) w[k] = W[k * D_F + f];
    const float bias = b[f];
    __syncthreads();
#pragma unroll
    for (int n = 0; n < 8; n++) {
        float acc = bias;
#pragma unroll
        for (int k = 0; k < D_IN; k++) acc = fmaf(xs[n * D_IN + k], w[k], acc);
        g_h[(nb + n) * D_F + f] = acc;
    }
}

// ---------------- K2: row_ptr via binary search on sorted tgt (int32) ----------------
__global__ void rowptr_kernel(const int* __restrict__ tgt) {
    int n = blockIdx.x * blockDim.x + threadIdx.x;
    if (n > N_NODES) return;
    if (n == N_NODES) { g_rowptr[n] = E_EDGES; return; }
    int lo = 0, hi = E_EDGES;
    while (lo < hi) {
        int mid = (lo + hi) >> 1;
        if (tgt[mid] < n) lo = mid + 1; else hi = mid;
    }
    g_rowptr[n] = lo;
}

// ---------------- K3: edge filter MLP + messages + raw attention ----------------
// Tile: 64 edges x 128 feats. Block 256 threads = 8 warps.
// Warp w owns edges w*8..w*8+7; lane owns feats lane*4..lane*4+3.
// Inner product loops use packed fma.rn.f32x2 (2 fp32 FMA / instr).
__global__ __launch_bounds__(256) void edge_kernel(
    const int* __restrict__ src,
    const float* __restrict__ edge_attr,
    const float* __restrict__ Wf1, const float* __restrict__ bf1,
    const float* __restrict__ Wf2, const float* __restrict__ bf2,
    const float* __restrict__ nbr,
    float* __restrict__ attn_out)
{
    __shared__ float sm[64 * D_F];      // t_s; front 64*64 floats doubles as ean_s
    __shared__ float norm_s[64];
    __shared__ float inv_s[64];
    float* ean_s = sm;
    float* t_s   = sm;

    const int tid   = threadIdx.x;
    const int lane  = tid & 31;
    const int w     = tid >> 5;
    const int ebase = blockIdx.x * 64;

    if (tid < 64) norm_s[tid] = 0.f;
    __syncthreads();

    // --- load edge_attr tile (contiguous 4096 floats), accumulate per-row sumsq ---
    float4 v[4];
    const float4* ea4 = (const float4*)(edge_attr + (size_t)ebase * D_G);
#pragma unroll
    for (int j = 0; j < 4; j++) {
        int p = tid + 256 * j;                 // float4 index 0..1023; row = p>>4
        v[j] = ea4[p];
        float ss = v[j].x * v[j].x + v[j].y * v[j].y + v[j].z * v[j].z + v[j].w * v[j].w;
        atomicAdd(&norm_s[p >> 4], ss);
    }
    __syncthreads();
    if (tid < 64) inv_s[tid] = 1.0f / (sqrtf(norm_s[tid]) + 1e-8f);
    __syncthreads();
#pragma unroll
    for (int j = 0; j < 4; j++) {
        int p = tid + 256 * j;
        float inv = inv_s[p >> 4];
        v[j].x *= inv; v[j].y *= inv; v[j].z *= inv; v[j].w *= inv;
        ((float4*)ean_s)[p] = v[j];
    }
    __syncthreads();

    // --- GEMM1: t = tanh(ean @ Wf1 + bf1); acc pairs (f0,f1),(f2,f3) per edge ---
    uint64_t acc2[8][2];
    {
        float4 b1 = *(const float4*)(bf1 + lane * 4);
        uint64_t b01 = pack2(b1.x, b1.y), b23 = pack2(b1.z, b1.w);
#pragma unroll
        for (int i = 0; i < 8; i++) { acc2[i][0] = b01; acc2[i][1] = b23; }
    }
    for (int k = 0; k < D_G; k++) {
        ulonglong2 wk2 = *(const ulonglong2*)(Wf1 + k * D_F + lane * 4);
#pragma unroll
        for (int i = 0; i < 8; i++) {
            float a = ean_s[(w * 8 + i) * D_G + k];   // warp-broadcast LDS
            uint64_t aa = pack2(a, a);
            ffma2(acc2[i][0], aa, wk2.x);
            ffma2(acc2[i][1], aa, wk2.y);
        }
    }
    __syncthreads();                // all ean reads done before overwrite
#pragma unroll
    for (int i = 0; i < 8; i++) {
        float x0, x1, x2, x3;
        unpack2(acc2[i][0], x0, x1);
        unpack2(acc2[i][1], x2, x3);
        float4 t4 = make_float4(tanhf(x0), tanhf(x1), tanhf(x2), tanhf(x3));
        ((float4*)(t_s + (w * 8 + i) * D_F))[lane] = t4;
    }
    __syncthreads();

    // --- GEMM2: filters = t @ Wf2 + bf2 ---
    {
        float4 b2 = *(const float4*)(bf2 + lane * 4);
        uint64_t b01 = pack2(b2.x, b2.y), b23 = pack2(b2.z, b2.w);
#pragma unroll
        for (int i = 0; i < 8; i++) { acc2[i][0] = b01; acc2[i][1] = b23; }
    }
    for (int k = 0; k < D_F; k++) {
        ulonglong2 wk2 = *(const ulonglong2*)(Wf2 + k * D_F + lane * 4);
#pragma unroll
        for (int i = 0; i < 8; i++) {
            float a = t_s[(w * 8 + i) * D_F + k];     // warp-broadcast LDS
            uint64_t aa = pack2(a, a);
            ffma2(acc2[i][0], aa, wk2.x);
            ffma2(acc2[i][1], aa, wk2.y);
        }
    }

    // --- messages = h[src] * filters; attn = messages . nbr_filter ---
    const float4 nbr4 = *(const float4*)(nbr + lane * 4);
    float p[8];
#pragma unroll
    for (int i = 0; i < 8; i++) {
        int e = ebase + w * 8 + i;
        int sn = src[e];
        float4 h4 = *(const float4*)(g_h + (size_t)sn * D_F + lane * 4);
        float f0, f1, f2, f3;
        unpack2(acc2[i][0], f0, f1);
        unpack2(acc2[i][1], f2, f3);
        float4 m;
        m.x = h4.x * f0; m.y = h4.y * f1;
        m.z = h4.z * f2; m.w = h4.w * f3;
        ((float4*)(g_messages + (size_t)e * D_F))[lane] = m;
        p[i] = m.x * nbr4.x + m.y * nbr4.y + m.z * nbr4.z + m.w * nbr4.w;
    }
#pragma unroll
    for (int off = 16; off; off >>= 1) {
#pragma unroll
        for (int i = 0; i < 8; i++)
            p[i] += __shfl_xor_sync(0xffffffffu, p[i], off);
    }
    if (lane == 0) {
#pragma unroll
        for (int i = 0; i < 8; i++) attn_out[ebase + w * 8 + i] = p[i];
    }
}

// ---------------- K4: per-node segment softmax + weighted aggregate ----------------
__global__ __launch_bounds__(256) void agg_kernel(const float* __restrict__ attn) {
    const int node = (blockIdx.x * blockDim.x + threadIdx.x) >> 5;
    const int lane = threadIdx.x & 31;
    if (node >= N_NODES) return;
    const int s = g_rowptr[node];
    const int e = g_rowptr[node + 1];

    float m = -INFINITY;
    for (int j = s + lane; j < e; j += 32) m = fmaxf(m, attn[j]);
#pragma unroll
    for (int off = 16; off; off >>= 1) m = fmaxf(m, __shfl_xor_sync(0xffffffffu, m, off));

    float ssum = 0.f;
    for (int j = s + lane; j < e; j += 32) ssum += expf(attn[j] - m);
#pragma unroll
    for (int off = 16; off; off >>= 1) ssum += __shfl_xor_sync(0xffffffffu, ssum, off);
    const float inv = (e > s) ? 1.0f / ssum : 0.0f;

    float4 acc = make_float4(0.f, 0.f, 0.f, 0.f);
    for (int j = s; j < e; j++) {
        float wgt = expf(attn[j] - m) * inv;
        float4 mm = ((const float4*)(g_messages + (size_t)j * D_F))[lane];
        acc.x = fmaf(wgt, mm.x, acc.x);
        acc.y = fmaf(wgt, mm.y, acc.y);
        acc.z = fmaf(wgt, mm.z, acc.z);
        acc.w = fmaf(wgt, mm.w, acc.w);
    }
    ((float4*)(g_agg + (size_t)node * D_F))[lane] = acc;
}

// ---------------- K5: out = tanh(agg @ Wo1 + bo1) @ Wo2 + bo2 ----------------
__global__ __launch_bounds__(256) void out_kernel(
    const float* __restrict__ Wo1, const float* __restrict__ bo1,
    const float* __restrict__ Wo2, const float* __restrict__ bo2,
    float* __restrict__ out)
{
    __shared__ float sm[64 * D_F];
    const int tid  = threadIdx.x;
    const int lane = tid & 31;
    const int w    = tid >> 5;
    const int nb   = blockIdx.x * 64;

    const float4* src4 = (const float4*)(g_agg + (size_t)nb * D_F);
#pragma unroll
    for (int j = 0; j < 8; j++)
        ((float4*)sm)[tid + 256 * j] = src4[tid + 256 * j];
    __syncthreads();

    // GEMM1: t = tanh(agg @ Wo1 + bo1), packed f32x2
    uint64_t acc2[8][2];
    {
        float4 b1 = *(const float4*)(bo1 + lane * 4);
        uint64_t b01 = pack2(b1.x, b1.y), b23 = pack2(b1.z, b1.w);
#pragma unroll
        for (int i = 0; i < 8; i++) { acc2[i][0] = b01; acc2[i][1] = b23; }
    }
    for (int k = 0; k < D_F; k++) {
        ulonglong2 wk2 = *(const ulonglong2*)(Wo1 + k * D_F + lane * 4);
#pragma unroll
        for (int i = 0; i < 8; i++) {
            float a = sm[(w * 8 + i) * D_F + k];
            uint64_t aa = pack2(a, a);
            ffma2(acc2[i][0], aa, wk2.x);
            ffma2(acc2[i][1], aa, wk2.y);
        }
    }
    __syncthreads();
#pragma unroll
    for (int i = 0; i < 8; i++) {
        float x0, x1, x2, x3;
        unpack2(acc2[i][0], x0, x1);
        unpack2(acc2[i][1], x2, x3);
        float4 t4 = make_float4(tanhf(x0), tanhf(x1), tanhf(x2), tanhf(x3));
        ((float4*)(sm + (w * 8 + i) * D_F))[lane] = t4;
    }
    __syncthreads();

    // GEMM2: out[64][32] = t @ Wo2 + bo2 ; lane = output feature
    float o[8];
    {
        float b2 = bo2[lane];
#pragma unroll
        for (int i = 0; i < 8; i++) o[i] = b2;
    }
    for (int k = 0; k < D_F; k++) {
        float wo = Wo2[k * D_IN + lane];
#pragma unroll
        for (int i = 0; i < 8; i++)
            o[i] = fmaf(sm[(w * 8 + i) * D_F + k], wo, o[i]);
    }
#pragma unroll
    for (int i = 0; i < 8; i++)
        out[(size_t)(nb + w * 8 + i) * D_IN + lane] = o[i];
}

// ---------------- launch ----------------
extern "C" void kernel_launch(void* const* d_in, const int* in_sizes, int n_in,
                              void* d_out, int out_size) {
    const float* x         = (const float*)d_in[0];
    const int*   edge_index= (const int*)d_in[1];     // int32 (JAX x64 disabled)
    const float* edge_attr = (const float*)d_in[2];
    const float* W_proj    = (const float*)d_in[3];
    const float* b_proj    = (const float*)d_in[4];
    const float* Wf1       = (const float*)d_in[5];
    const float* bf1       = (const float*)d_in[6];
    const float* Wf2       = (const float*)d_in[7];
    const float* bf2       = (const float*)d_in[8];
    const float* nbr       = (const float*)d_in[9];
    const float* Wo1       = (const float*)d_in[10];
    const float* bo1       = (const float*)d_in[11];
    const float* Wo2       = (const float*)d_in[12];
    const float* bo2       = (const float*)d_in[13];

    float* out      = (float*)d_out;
    float* attn_out = out + (size_t)N_NODES * D_IN;   // tuple (out, attn) concat

    const int* src = edge_index;
    const int* tgt = edge_index + E_EDGES;

    proj_kernel<<<N_NODES / 8, 128>>>(x, W_proj, b_proj);
    rowptr_kernel<<<(N_NODES + 1 + 255) / 256, 256>>>(tgt);
    edge_kernel<<<E_EDGES / 64, 256>>>(src, edge_attr, Wf1, bf1, Wf2, bf2, nbr, attn_out);
    agg_kernel<<<(N_NODES * 32) / 256, 256>>>(attn_out);
    out_kernel<<<N_NODES / 64, 256>>>(Wo1, bo1, Wo2, bo2, out);
}